// round 14
// baseline (speedup 1.0000x reference)
#include <cuda_runtime.h>
#include <cstdint>
#include <math.h>

#define LL 512
#define BB 32
#define KT 12
#define MR (LL*BB)

// ---------------------------------------------------------------------------
// Scratch + staging (static; no allocations)
// ---------------------------------------------------------------------------
__device__ float g_x0[MR * 256];
__device__ float g_buf[2][(size_t)MR * 512];
__device__ float g_G[(size_t)2048 * MR];
__device__ float g_feats[(size_t)MR * KT];
__device__ int   g_tags[MR];

__device__ int   g_i64;    // integer tensors are 64-bit
__device__ int   g_f64;    // float tensors are 64-bit

__device__ int   s_tok[16384];
__device__ float s_emb[12800000];
__device__ float s_wih0[524288];
__device__ float s_whh0[524288];
__device__ float s_b0[2048];
__device__ float s_wih[3145728];
__device__ float s_whh[1572864];
__device__ float s_b[6144];
__device__ float s_fcw[6144];
__device__ float s_fcb[12];
__device__ float s_tr[144];

// ---------------------------------------------------------------------------
// Dtype sniffers (deterministic; read only within the smaller-world bounds)
// ---------------------------------------------------------------------------
__global__ void k_init_flags() {
    if (threadIdx.x == 0) { g_i64 = 1; g_f64 = 0; }
}

// Scan first 8192 int32-pairs of tokens (16384 int32 = safe in both worlds).
// int64 world: every pair = (v in [0,50000), 0). Any violation -> int32.
__global__ void k_sniff_tok(const void* __restrict__ tok) {
    const int* p = (const int*)tok;
    int i = blockIdx.x * blockDim.x + threadIdx.x;   // pair index
    if (i < 8192) {
        int lo = p[2 * i], hi = p[2 * i + 1];
        if (hi != 0 || lo < 0 || lo >= 50000) g_i64 = 0;
    }
}

// Scan first 16384 float32 views of embed (safe in both worlds).
// float32 world: all |v| < 100 (data is N(0,1)*0.1). Violations -> f64.
__global__ void k_sniff_f(const void* __restrict__ emb) {
    const float* p = (const float*)emb;
    int i = blockIdx.x * blockDim.x + threadIdx.x;
    if (i < 16384) {
        float v = p[i];
        if (!isfinite(v) || fabsf(v) > 100.f) g_f64 = 1;
    }
}

// ---------------------------------------------------------------------------
// Converters
// ---------------------------------------------------------------------------
__global__ void k_cvt_tok(const void* __restrict__ src) {
    int i = blockIdx.x * blockDim.x + threadIdx.x;
    if (i >= 16384) return;
    if (g_i64) s_tok[i] = (int)((const long long*)src)[i];
    else       s_tok[i] = ((const int*)src)[i];
}

__global__ void k_cvt_f(float* __restrict__ dst, const void* __restrict__ src, int n) {
    int i  = blockIdx.x * blockDim.x + threadIdx.x;
    int st = gridDim.x * blockDim.x;
    if (g_f64) {
        const double* s = (const double*)src;
        for (; i < n; i += st) dst[i] = (float)s[i];
    } else {
        const float* s = (const float*)src;
        for (; i < n; i += st) dst[i] = s[i];
    }
}

// ---------------------------------------------------------------------------
// Pipeline (honest math, off staged f32/i32 inputs)
// ---------------------------------------------------------------------------
__global__ void k_embed() {
    int idx = blockIdx.x * blockDim.x + threadIdx.x;
    if (idx >= MR * 256) return;
    int m = idx >> 8, e = idx & 255;
    int t = m >> 5, b = m & 31;
    g_x0[idx] = s_emb[(size_t)s_tok[b * LL + t] * 256 + e];
}

__global__ void k_gemm16(const float* __restrict__ A, const float* __restrict__ W,
                         const float* __restrict__ bias, int Kin) {
    __shared__ float As[16][17];
    __shared__ float Ws[16][17];
    int tx = threadIdx.x, ty = threadIdx.y;
    int n0 = blockIdx.x * 16, m0 = blockIdx.y * 16;
    float acc = 0.f;
    for (int k0 = 0; k0 < Kin; k0 += 16) {
        As[ty][tx] = A[(size_t)(m0 + ty) * Kin + k0 + tx];
        Ws[ty][tx] = W[(size_t)(n0 + ty) * Kin + k0 + tx];
        __syncthreads();
#pragma unroll
        for (int kk = 0; kk < 16; kk++) acc += As[ty][kk] * Ws[tx][kk];
        __syncthreads();
    }
    g_G[(size_t)(n0 + tx) * MR + (m0 + ty)] = acc + bias[n0 + tx];
}

__global__ void __launch_bounds__(256) k_recur(const float* __restrict__ Whh,
                                               float* __restrict__ outbuf) {
    __shared__ float h_sh[256];
    int j = threadIdx.x;
    int d = blockIdx.x >> 5;
    int b = blockIdx.x & 31;

    const float* W0 = Whh + ((size_t)d * 1024 + 0 * 256 + j) * 256;
    const float* W1 = Whh + ((size_t)d * 1024 + 1 * 256 + j) * 256;
    const float* W2 = Whh + ((size_t)d * 1024 + 2 * 256 + j) * 256;
    const float* W3 = Whh + ((size_t)d * 1024 + 3 * 256 + j) * 256;

    float c = 0.f;
    h_sh[j] = 0.f;
    __syncthreads();

    for (int s = 0; s < LL; s++) {
        int t = d ? (LL - 1 - s) : s;
        float a0 = 0.f, a1 = 0.f, a2 = 0.f, a3 = 0.f;
#pragma unroll 4
        for (int k = 0; k < 256; k++) {
            float hv = h_sh[k];
            a0 += W0[k] * hv; a1 += W1[k] * hv;
            a2 += W2[k] * hv; a3 += W3[k] * hv;
        }
        size_t m = (size_t)t * 32 + b;
        float gi = a0 + g_G[((size_t)(d * 1024 + 0 * 256 + j)) * MR + m];
        float gf = a1 + g_G[((size_t)(d * 1024 + 1 * 256 + j)) * MR + m];
        float gg = a2 + g_G[((size_t)(d * 1024 + 2 * 256 + j)) * MR + m];
        float go = a3 + g_G[((size_t)(d * 1024 + 3 * 256 + j)) * MR + m];

        float ig = 1.f / (1.f + expf(-gi));
        float fg = 1.f / (1.f + expf(-gf));
        float gv = tanhf(gg);
        float og = 1.f / (1.f + expf(-go));
        c = fg * c + ig * gv;
        float h = og * tanhf(c);
        __syncthreads();
        h_sh[j] = h;
        outbuf[m * 512 + d * 256 + j] = h;
        __syncthreads();
    }
}

__global__ void k_fc(const float* __restrict__ X) {
    int w    = (blockIdx.x * blockDim.x + threadIdx.x) >> 5;
    int lane = threadIdx.x & 31;
    if (w >= MR) return;
    const float* x = X + (size_t)w * 512;
    float acc[KT];
#pragma unroll
    for (int c = 0; c < KT; c++) acc[c] = 0.f;
    for (int k = lane; k < 512; k += 32) {
        float xv = x[k];
#pragma unroll
        for (int c = 0; c < KT; c++) acc[c] += xv * s_fcw[c * 512 + k];
    }
#pragma unroll
    for (int off = 16; off; off >>= 1)
#pragma unroll
        for (int c = 0; c < KT; c++) acc[c] += __shfl_down_sync(0xffffffffu, acc[c], off);
    if (lane == 0) {
        int b = w & 31, t = w >> 5;
        float* o = g_feats + ((size_t)b * LL + t) * KT;
#pragma unroll
        for (int c = 0; c < KT; c++) o[c] = acc[c] + s_fcb[c];
    }
}

__global__ void k_viterbi() {
    __shared__ float tr[KT][KT];
    __shared__ float sc[2][KT];
    __shared__ unsigned char bp[LL - 1][KT];

    int b = blockIdx.x, tid = threadIdx.x;
    for (int i = tid; i < KT * KT; i += 32) ((float*)tr)[i] = s_tr[i];
    __syncwarp();

    const float* f = g_feats + (size_t)b * LL * KT;
    if (tid < KT) sc[0][tid] = f[tid] + tr[10][tid];   // START = 10
    __syncwarp();

    for (int t = 1; t < LL; t++) {
        int cur = t & 1, prv = cur ^ 1;
        if (tid < KT) {
            float best = -1e30f; int arg = 0;
#pragma unroll
            for (int p = 0; p < KT; p++) {
                float v = sc[prv][p] + tr[p][tid];
                if (v > best) { best = v; arg = p; }
            }
            bp[t - 1][tid] = (unsigned char)arg;
            sc[cur][tid]   = best + f[t * KT + tid];
        }
        __syncwarp();
    }
    if (tid == 0) {
        float best = -1e30f; int st = 0;
#pragma unroll
        for (int c = 0; c < KT; c++) {
            float v = sc[(LL - 1) & 1][c] + tr[c][11];  // STOP = 11
            if (v > best) { best = v; st = c; }
        }
        g_tags[b * LL + (LL - 1)] = st;
        for (int i = LL - 2; i >= 0; i--) {
            st = bp[i][st];
            g_tags[b * LL + i] = st;
        }
    }
}

// ---------------------------------------------------------------------------
// THE FIX: emit tags as FLOATING-POINT values. 13 rounds of exactly-1.0
// rel_err are explained by an fp32 output buffer: integer stores 0..11 read
// back as denormals ~1e-44 ~= 0 -> norm(0-ref)/norm(ref) == 1.000000 exactly,
// invariant to everything we wrote. Width follows the float canonicalization
// sniff (f64 world -> double output).
// ---------------------------------------------------------------------------
__global__ void k_out(void* __restrict__ out) {
    int i = blockIdx.x * blockDim.x + threadIdx.x;
    if (i >= MR) return;
    if (g_f64) ((double*)out)[i] = (double)g_tags[i];
    else       ((float*)out)[i]  = (float)g_tags[i];
}

// ---------------------------------------------------------------------------
extern "C" void kernel_launch(void* const* d_in, const int* in_sizes, int n_in,
                              void* d_out, int out_size) {
    const void* tokens = d_in[0];
    const void* embed  = d_in[1];
    const void* w_ih0  = d_in[2];
    const void* w_hh0  = d_in[3];
    const void* b0     = d_in[4];
    const void* w_ih   = d_in[5];
    const void* w_hh   = d_in[6];
    const void* bvec   = d_in[7];
    const void* fc_w   = d_in[8];
    const void* fc_b   = d_in[9];
    const void* trans  = d_in[10];

    float *p_emb, *p_wih0, *p_whh0, *p_b0, *p_wih, *p_whh, *p_b, *p_fcw, *p_fcb, *p_tr;
    float *px0, *pbuf;
    cudaGetSymbolAddress((void**)&p_emb,  s_emb);
    cudaGetSymbolAddress((void**)&p_wih0, s_wih0);
    cudaGetSymbolAddress((void**)&p_whh0, s_whh0);
    cudaGetSymbolAddress((void**)&p_b0,   s_b0);
    cudaGetSymbolAddress((void**)&p_wih,  s_wih);
    cudaGetSymbolAddress((void**)&p_whh,  s_whh);
    cudaGetSymbolAddress((void**)&p_b,    s_b);
    cudaGetSymbolAddress((void**)&p_fcw,  s_fcw);
    cudaGetSymbolAddress((void**)&p_fcb,  s_fcb);
    cudaGetSymbolAddress((void**)&p_tr,   s_tr);
    cudaGetSymbolAddress((void**)&px0,    g_x0);
    cudaGetSymbolAddress((void**)&pbuf,   g_buf);
    float* pbuf0 = pbuf;
    float* pbuf1 = pbuf + (size_t)MR * 512;

    // 1) Sniff dtypes
    k_init_flags<<<1, 32>>>();
    k_sniff_tok<<<32, 256>>>(tokens);
    k_sniff_f<<<64, 256>>>(embed);

    // 2) Convert all inputs to canonical f32/i32 staging
    k_cvt_tok<<<64, 256>>>(tokens);
    k_cvt_f<<<512, 256>>>(p_emb,  embed, 12800000);
    k_cvt_f<<<128, 256>>>(p_wih0, w_ih0, 524288);
    k_cvt_f<<<128, 256>>>(p_whh0, w_hh0, 524288);
    k_cvt_f<<<8, 256>>>(p_b0, b0, 2048);
    k_cvt_f<<<256, 256>>>(p_wih, w_ih, 3145728);
    k_cvt_f<<<128, 256>>>(p_whh, w_hh, 1572864);
    k_cvt_f<<<8, 256>>>(p_b, bvec, 6144);
    k_cvt_f<<<8, 256>>>(p_fcw, fc_w, 6144);
    k_cvt_f<<<1, 32>>>(p_fcb, fc_b, 12);
    k_cvt_f<<<1, 256>>>(p_tr, trans, 144);

    // 3) Pipeline
    dim3 tile(16, 16);
    dim3 ggrid(2048 / 16, MR / 16);

    k_embed<<<MR, 256>>>();
    k_gemm16<<<ggrid, tile>>>(px0, p_wih0, p_b0, 256);
    k_recur<<<64, 256>>>(p_whh0, pbuf0);

    const float* ins[3]  = {pbuf0, pbuf1, pbuf0};
    float*       outs[3] = {pbuf1, pbuf0, pbuf1};
    for (int l = 1; l <= 3; l++) {
        k_gemm16<<<ggrid, tile>>>(ins[l - 1],
                                  p_wih + (size_t)(l - 1) * 2 * 1024 * 512,
                                  p_b + (size_t)(l - 1) * 2 * 1024, 512);
        k_recur<<<64, 256>>>(p_whh + (size_t)(l - 1) * 2 * 1024 * 256, outs[l - 1]);
    }

    k_fc<<<2048, 256>>>(pbuf1);
    k_viterbi<<<BB, 32>>>();
    k_out<<<64, 256>>>(d_out);
}

// round 15
// speedup vs baseline: 18.4770x; 18.4770x over previous
#include <cuda_runtime.h>
#include <cstdint>
#include <math.h>

#define LL 512
#define BB 32
#define KT 12
#define MR (LL*BB)

// ---------------------------------------------------------------------------
// Scratch + staging (static; no allocations)
// ---------------------------------------------------------------------------
__device__ float g_x0[MR * 256];
__device__ float g_buf[2][(size_t)MR * 512];
__device__ float g_G[(size_t)2048 * MR];        // gate-major [n][m], bias included
__device__ float g_feats[(size_t)MR * KT];
__device__ int   g_tags[MR];
__device__ float g_hbuf[2][2][256][32];         // h double-buffer [par][dir][j][b]
__device__ unsigned g_arrive[2];                // monotonic per-direction counters

__device__ int   g_i64;
__device__ int   g_f64;

__device__ int   s_tok[16384];
__device__ float s_emb[12800000];
__device__ float s_wih0[524288];
__device__ float s_whh0[524288];
__device__ float s_b0[2048];
__device__ float s_wih[3145728];
__device__ float s_whh[1572864];
__device__ float s_b[6144];
__device__ float s_fcw[6144];
__device__ float s_fcb[12];
__device__ float s_tr[144];

// ---------------------------------------------------------------------------
// Dtype sniffers + converters (proven in R14)
// ---------------------------------------------------------------------------
__global__ void k_init_flags() {
    if (threadIdx.x == 0) { g_i64 = 1; g_f64 = 0; g_arrive[0] = 0u; g_arrive[1] = 0u; }
}

__global__ void k_sniff_tok(const void* __restrict__ tok) {
    const int* p = (const int*)tok;
    int i = blockIdx.x * blockDim.x + threadIdx.x;
    if (i < 8192) {
        int lo = p[2 * i], hi = p[2 * i + 1];
        if (hi != 0 || lo < 0 || lo >= 50000) g_i64 = 0;
    }
}

__global__ void k_sniff_f(const void* __restrict__ emb) {
    const float* p = (const float*)emb;
    int i = blockIdx.x * blockDim.x + threadIdx.x;
    if (i < 16384) {
        float v = p[i];
        if (!isfinite(v) || fabsf(v) > 100.f) g_f64 = 1;
    }
}

__global__ void k_cvt_tok(const void* __restrict__ src) {
    int i = blockIdx.x * blockDim.x + threadIdx.x;
    if (i >= 16384) return;
    if (g_i64) s_tok[i] = (int)((const long long*)src)[i];
    else       s_tok[i] = ((const int*)src)[i];
}

__global__ void k_cvt_f(float* __restrict__ dst, const void* __restrict__ src, int n) {
    int i  = blockIdx.x * blockDim.x + threadIdx.x;
    int st = gridDim.x * blockDim.x;
    if (g_f64) {
        const double* s = (const double*)src;
        for (; i < n; i += st) dst[i] = (float)s[i];
    } else {
        const float* s = (const float*)src;
        for (; i < n; i += st) dst[i] = s[i];
    }
}

__global__ void k_reset() { if (threadIdx.x < 2) g_arrive[threadIdx.x] = 0u; }

// ---------------------------------------------------------------------------
// Embedding (vectorized): g_x0[t*32+b][e] = s_emb[s_tok[b][t]][e]
// ---------------------------------------------------------------------------
__global__ void k_embed() {
    int w    = (blockIdx.x * blockDim.x + threadIdx.x) >> 5;
    int lane = threadIdx.x & 31;
    if (w >= MR) return;
    int t = w >> 5, b = w & 31;
    const float4* src = (const float4*)(s_emb + (size_t)s_tok[b * LL + t] * 256);
    float4*       dst = (float4*)(g_x0 + (size_t)w * 256);
    dst[lane]      = src[lane];
    dst[lane + 32] = src[lane + 32];
}

// ---------------------------------------------------------------------------
// Register-tiled GEMM: g_G[n][m] = A[m]·W[n] + bias[n]
// BM=128 (by), BN=128 (bx), BK=16, 256 threads, 8x8 acc, direct writeback.
// ---------------------------------------------------------------------------
__global__ void __launch_bounds__(256) k_igemm(const float* __restrict__ A,
                                               const float* __restrict__ W,
                                               const float* __restrict__ bias,
                                               int Kin) {
    __shared__ float As[16][132];
    __shared__ float Ws[16][132];

    int tid = threadIdx.x;
    int m0 = blockIdx.y * 128, n0 = blockIdx.x * 128;
    int kc4 = tid & 3, ml = tid >> 2;
    int tx = tid & 15, ty = tid >> 4;

    float acc[8][8];
#pragma unroll
    for (int i = 0; i < 8; i++)
#pragma unroll
        for (int j = 0; j < 8; j++) acc[i][j] = 0.f;

    for (int k0 = 0; k0 < Kin; k0 += 16) {
        float4 a0 = *(const float4*)(A + (size_t)(m0 + ml) * Kin + k0 + kc4 * 4);
        float4 a1 = *(const float4*)(A + (size_t)(m0 + ml + 64) * Kin + k0 + kc4 * 4);
        float4 w0 = *(const float4*)(W + (size_t)(n0 + ml) * Kin + k0 + kc4 * 4);
        float4 w1 = *(const float4*)(W + (size_t)(n0 + ml + 64) * Kin + k0 + kc4 * 4);
        __syncthreads();
        As[kc4 * 4 + 0][ml] = a0.x; As[kc4 * 4 + 1][ml] = a0.y;
        As[kc4 * 4 + 2][ml] = a0.z; As[kc4 * 4 + 3][ml] = a0.w;
        As[kc4 * 4 + 0][ml + 64] = a1.x; As[kc4 * 4 + 1][ml + 64] = a1.y;
        As[kc4 * 4 + 2][ml + 64] = a1.z; As[kc4 * 4 + 3][ml + 64] = a1.w;
        Ws[kc4 * 4 + 0][ml] = w0.x; Ws[kc4 * 4 + 1][ml] = w0.y;
        Ws[kc4 * 4 + 2][ml] = w0.z; Ws[kc4 * 4 + 3][ml] = w0.w;
        Ws[kc4 * 4 + 0][ml + 64] = w1.x; Ws[kc4 * 4 + 1][ml + 64] = w1.y;
        Ws[kc4 * 4 + 2][ml + 64] = w1.z; Ws[kc4 * 4 + 3][ml + 64] = w1.w;
        __syncthreads();
#pragma unroll
        for (int kk = 0; kk < 16; kk++) {
            float av[8], bv[8];
            *(float4*)(av)     = *(const float4*)&As[kk][ty * 8];
            *(float4*)(av + 4) = *(const float4*)&As[kk][ty * 8 + 4];
            *(float4*)(bv)     = *(const float4*)&Ws[kk][tx * 8];
            *(float4*)(bv + 4) = *(const float4*)&Ws[kk][tx * 8 + 4];
#pragma unroll
            for (int i = 0; i < 8; i++)
#pragma unroll
                for (int j = 0; j < 8; j++) acc[i][j] += av[i] * bv[j];
        }
    }

#pragma unroll
    for (int j = 0; j < 8; j++) {
        int n = n0 + tx * 8 + j;
        float bb = bias[n];
#pragma unroll
        for (int i = 0; i < 8; i++)
            g_G[(size_t)n * MR + (m0 + ty * 8 + i)] = acc[i][j] + bb;
    }
}

// ---------------------------------------------------------------------------
// Monotonic per-direction grid barrier (64 blocks/direction, no reuse races)
// ---------------------------------------------------------------------------
__device__ __forceinline__ void dir_barrier(int d, unsigned target) {
    __threadfence();
    __syncthreads();
    if (threadIdx.x == 0) {
        atomicAdd(&g_arrive[d], 1u);
        volatile unsigned* va = &g_arrive[d];
        while (*va < target) __nanosleep(64);
    }
    __syncthreads();
    __threadfence();
}

// ---------------------------------------------------------------------------
// Persistent LSTM recurrence: 128 blocks, d = bx/64, block owns 4 hidden
// units (16 gate rows) x 32 batches; Whh slice SMEM-resident (18KB).
// ---------------------------------------------------------------------------
__global__ void __launch_bounds__(256) k_recur(const float* __restrict__ Whh,
                                               float* __restrict__ outbuf) {
    extern __shared__ float dsm[];
    float (*wT)[18]        = (float(*)[18])dsm;                               // [256][18]
    float (*h_sh)[32]      = (float(*)[32])(dsm + 256 * 18);                  // [256][32]
    float (*gpart)[16][32] = (float(*)[16][32])(dsm + 256 * 18 + 256 * 32);   // [2][16][32]
    float (*c_st)[32]      = (float(*)[32])(dsm + 256 * 18 + 256 * 32 + 2 * 16 * 32); // [4][32]

    int tid = threadIdx.x;
    int d   = blockIdx.x >> 6;
    int bi  = blockIdx.x & 63;
    int j0  = bi * 4;

    // Load Whh slice transposed: wT[k][r], r = q*4+jj -> gate row q*256+j0+jj
    {
        int r = tid >> 4, cp = tid & 15;
        int q = r >> 2, jj = r & 3;
        const float* wrow = Whh + ((size_t)d * 1024 + q * 256 + j0 + jj) * 256;
#pragma unroll
        for (int c4 = 0; c4 < 4; c4++) {
            float4 v = *(const float4*)(wrow + cp * 16 + c4 * 4);
            wT[cp * 16 + c4 * 4 + 0][r] = v.x;
            wT[cp * 16 + c4 * 4 + 1][r] = v.y;
            wT[cp * 16 + c4 * 4 + 2][r] = v.z;
            wT[cp * 16 + c4 * 4 + 3][r] = v.w;
        }
        if (tid < 128) c_st[tid >> 5][tid & 31] = 0.f;
    }
    __syncthreads();

    int kh  = tid >> 7;
    int rem = tid & 127;
    int gp  = rem >> 4;
    int bp  = rem & 15;
    int b0  = bp * 2, g0l = gp * 2;

    for (int s = 0; s < LL; s++) {
        int t = d ? (LL - 1 - s) : s;

        // Phase 1: stage h_prev ([j][b] layout matches g_hbuf)
        if (s == 0) {
            for (int i = tid; i < 256 * 32; i += 256) ((float*)h_sh)[i] = 0.f;
        } else {
            const float4* src = (const float4*)&g_hbuf[s & 1][d][0][0];
            float4*       dst = (float4*)&h_sh[0][0];
            for (int i = tid; i < 2048; i += 256) dst[i] = __ldcg(src + i);
        }
        __syncthreads();

        // Phase 2: partial dots (2 gate rows x 2 batches x half-k per thread)
        float a00 = 0.f, a01 = 0.f, a10 = 0.f, a11 = 0.f;
        for (int k = kh * 128; k < kh * 128 + 128; k++) {
            float2 hv = *(const float2*)&h_sh[k][b0];
            float w0 = wT[k][g0l], w1 = wT[k][g0l + 1];
            a00 += w0 * hv.x; a01 += w0 * hv.y;
            a10 += w1 * hv.x; a11 += w1 * hv.y;
        }
        gpart[kh][g0l][b0]         = a00;
        gpart[kh][g0l][b0 + 1]     = a01;
        gpart[kh][g0l + 1][b0]     = a10;
        gpart[kh][g0l + 1][b0 + 1] = a11;
        __syncthreads();

        // Phase 3: cell update (128 threads: 4 hidden x 32 batches)
        if (tid < 128) {
            int jj = tid >> 5, b = tid & 31;
            float gate[4];
#pragma unroll
            for (int q = 0; q < 4; q++) {
                int r = q * 4 + jj;
                size_t gi = ((size_t)d * 1024 + q * 256 + j0 + jj) * MR + (size_t)t * 32 + b;
                gate[q] = gpart[0][r][b] + gpart[1][r][b] + g_G[gi];
            }
            float ig = 1.f / (1.f + expf(-gate[0]));
            float fg = 1.f / (1.f + expf(-gate[1]));
            float gg = tanhf(gate[2]);
            float og = 1.f / (1.f + expf(-gate[3]));
            float c  = fg * c_st[jj][b] + ig * gg;
            c_st[jj][b] = c;
            float h = og * tanhf(c);
            g_hbuf[(s + 1) & 1][d][j0 + jj][b] = h;
            outbuf[(size_t)(t * 32 + b) * 512 + d * 256 + j0 + jj] = h;
        }
        dir_barrier(d, 64u * (unsigned)(s + 1));
    }
}

// ---------------------------------------------------------------------------
__global__ void k_fc(const float* __restrict__ X) {
    int w    = (blockIdx.x * blockDim.x + threadIdx.x) >> 5;
    int lane = threadIdx.x & 31;
    if (w >= MR) return;
    const float* x = X + (size_t)w * 512;
    float acc[KT];
#pragma unroll
    for (int c = 0; c < KT; c++) acc[c] = 0.f;
    for (int k = lane; k < 512; k += 32) {
        float xv = x[k];
#pragma unroll
        for (int c = 0; c < KT; c++) acc[c] += xv * s_fcw[c * 512 + k];
    }
#pragma unroll
    for (int off = 16; off; off >>= 1)
#pragma unroll
        for (int c = 0; c < KT; c++) acc[c] += __shfl_down_sync(0xffffffffu, acc[c], off);
    if (lane == 0) {
        int b = w & 31, t = w >> 5;
        float* o = g_feats + ((size_t)b * LL + t) * KT;
#pragma unroll
        for (int c = 0; c < KT; c++) o[c] = acc[c] + s_fcb[c];
    }
}

// ---------------------------------------------------------------------------
__global__ void k_viterbi() {
    __shared__ float tr[KT][KT];
    __shared__ float sc[2][KT];
    __shared__ unsigned char bp[LL - 1][KT];

    int b = blockIdx.x, tid = threadIdx.x;
    for (int i = tid; i < KT * KT; i += 32) ((float*)tr)[i] = s_tr[i];
    __syncwarp();

    const float* f = g_feats + (size_t)b * LL * KT;
    if (tid < KT) sc[0][tid] = f[tid] + tr[10][tid];   // START = 10
    __syncwarp();

    for (int t = 1; t < LL; t++) {
        int cur = t & 1, prv = cur ^ 1;
        if (tid < KT) {
            float best = -1e30f; int arg = 0;
#pragma unroll
            for (int p = 0; p < KT; p++) {
                float v = sc[prv][p] + tr[p][tid];
                if (v > best) { best = v; arg = p; }
            }
            bp[t - 1][tid] = (unsigned char)arg;
            sc[cur][tid]   = best + f[t * KT + tid];
        }
        __syncwarp();
    }
    if (tid == 0) {
        float best = -1e30f; int st = 0;
#pragma unroll
        for (int c = 0; c < KT; c++) {
            float v = sc[(LL - 1) & 1][c] + tr[c][11];  // STOP = 11
            if (v > best) { best = v; st = c; }
        }
        g_tags[b * LL + (LL - 1)] = st;
        for (int i = LL - 2; i >= 0; i--) {
            st = bp[i][st];
            g_tags[b * LL + i] = st;
        }
    }
}

// Float output — THE fix from R14.
__global__ void k_out(void* __restrict__ out) {
    int i = blockIdx.x * blockDim.x + threadIdx.x;
    if (i >= MR) return;
    if (g_f64) ((double*)out)[i] = (double)g_tags[i];
    else       ((float*)out)[i]  = (float)g_tags[i];
}

// ---------------------------------------------------------------------------
extern "C" void kernel_launch(void* const* d_in, const int* in_sizes, int n_in,
                              void* d_out, int out_size) {
    const void* tokens = d_in[0];
    const void* embed  = d_in[1];
    const void* w_ih0  = d_in[2];
    const void* w_hh0  = d_in[3];
    const void* b0     = d_in[4];
    const void* w_ih   = d_in[5];
    const void* w_hh   = d_in[6];
    const void* bvec   = d_in[7];
    const void* fc_w   = d_in[8];
    const void* fc_b   = d_in[9];
    const void* trans  = d_in[10];

    float *p_emb, *p_wih0, *p_whh0, *p_b0, *p_wih, *p_whh, *p_b, *p_fcw, *p_fcb, *p_tr;
    float *px0, *pbuf;
    cudaGetSymbolAddress((void**)&p_emb,  s_emb);
    cudaGetSymbolAddress((void**)&p_wih0, s_wih0);
    cudaGetSymbolAddress((void**)&p_whh0, s_whh0);
    cudaGetSymbolAddress((void**)&p_b0,   s_b0);
    cudaGetSymbolAddress((void**)&p_wih,  s_wih);
    cudaGetSymbolAddress((void**)&p_whh,  s_whh);
    cudaGetSymbolAddress((void**)&p_b,    s_b);
    cudaGetSymbolAddress((void**)&p_fcw,  s_fcw);
    cudaGetSymbolAddress((void**)&p_fcb,  s_fcb);
    cudaGetSymbolAddress((void**)&p_tr,   s_tr);
    cudaGetSymbolAddress((void**)&px0,    g_x0);
    cudaGetSymbolAddress((void**)&pbuf,   g_buf);
    float* pbuf0 = pbuf;
    float* pbuf1 = pbuf + (size_t)MR * 512;

    const int recur_smem = (256 * 18 + 256 * 32 + 2 * 16 * 32 + 4 * 32) * (int)sizeof(float);
    cudaFuncSetAttribute(k_recur, cudaFuncAttributeMaxDynamicSharedMemorySize, recur_smem);

    // 1) Sniff + convert
    k_init_flags<<<1, 32>>>();
    k_sniff_tok<<<32, 256>>>(tokens);
    k_sniff_f<<<64, 256>>>(embed);
    k_cvt_tok<<<64, 256>>>(tokens);
    k_cvt_f<<<512, 256>>>(p_emb,  embed, 12800000);
    k_cvt_f<<<128, 256>>>(p_wih0, w_ih0, 524288);
    k_cvt_f<<<128, 256>>>(p_whh0, w_hh0, 524288);
    k_cvt_f<<<8, 256>>>(p_b0, b0, 2048);
    k_cvt_f<<<256, 256>>>(p_wih, w_ih, 3145728);
    k_cvt_f<<<128, 256>>>(p_whh, w_hh, 1572864);
    k_cvt_f<<<8, 256>>>(p_b, bvec, 6144);
    k_cvt_f<<<8, 256>>>(p_fcw, fc_w, 6144);
    k_cvt_f<<<1, 32>>>(p_fcb, fc_b, 12);
    k_cvt_f<<<1, 256>>>(p_tr, trans, 144);

    // 2) Pipeline
    k_embed<<<2048, 256>>>();

    k_igemm<<<dim3(16, 128), 256>>>(px0, p_wih0, p_b0, 256);
    k_reset<<<1, 32>>>();
    k_recur<<<128, 256, recur_smem>>>(p_whh0, pbuf0);

    const float* ins[3]  = {pbuf0, pbuf1, pbuf0};
    float*       outs[3] = {pbuf1, pbuf0, pbuf1};
    for (int l = 1; l <= 3; l++) {
        k_igemm<<<dim3(16, 128), 256>>>(ins[l - 1],
                                        p_wih + (size_t)(l - 1) * 2 * 1024 * 512,
                                        p_b + (size_t)(l - 1) * 2 * 1024, 512);
        k_reset<<<1, 32>>>();
        k_recur<<<128, 256, recur_smem>>>(p_whh + (size_t)(l - 1) * 2 * 1024 * 256,
                                          outs[l - 1]);
    }

    k_fc<<<2048, 256>>>(pbuf1);
    k_viterbi<<<BB, 32>>>();
    k_out<<<64, 256>>>(d_out);
}

// round 16
// speedup vs baseline: 19.5639x; 1.0588x over previous
#include <cuda_runtime.h>
#include <cstdint>
#include <math.h>

#define LL 512
#define BB 32
#define KT 12
#define MR (LL*BB)

// ---------------------------------------------------------------------------
// Scratch + staging (static; no allocations)
// ---------------------------------------------------------------------------
__device__ float g_x0[MR * 256];
__device__ float g_buf[2][(size_t)MR * 512];
__device__ float g_G[(size_t)2048 * MR];        // gate-major [n][m], bias included
__device__ float g_feats[(size_t)MR * KT];
__device__ int   g_tags[MR];
__device__ float g_hbuf[2][2][256][32];         // h double-buffer [par][dir][j][b]
__device__ unsigned g_arrive[2];

__device__ int   g_i64;
__device__ int   g_f64;

__device__ int   s_tok[16384];
__device__ float s_wih0[524288];
__device__ float s_whh0[524288];
__device__ float s_b0[2048];
__device__ float s_wih[3145728];
__device__ float s_whh[1572864];
__device__ float s_b[6144];
__device__ float s_fcw[6144];
__device__ float s_fcb[12];
__device__ float s_tr[144];

// ---------------------------------------------------------------------------
// Dtype sniffers + converters (proven in R14/R15)
// ---------------------------------------------------------------------------
__global__ void k_init_flags() {
    if (threadIdx.x == 0) { g_i64 = 1; g_f64 = 0; g_arrive[0] = 0u; g_arrive[1] = 0u; }
}

__global__ void k_sniff_tok(const void* __restrict__ tok) {
    const int* p = (const int*)tok;
    int i = blockIdx.x * blockDim.x + threadIdx.x;
    if (i < 8192) {
        int lo = p[2 * i], hi = p[2 * i + 1];
        if (hi != 0 || lo < 0 || lo >= 50000) g_i64 = 0;
    }
}

__global__ void k_sniff_f(const void* __restrict__ emb) {
    const float* p = (const float*)emb;
    int i = blockIdx.x * blockDim.x + threadIdx.x;
    if (i < 16384) {
        float v = p[i];
        if (!isfinite(v) || fabsf(v) > 100.f) g_f64 = 1;
    }
}

__global__ void k_cvt_tok(const void* __restrict__ src) {
    int i = blockIdx.x * blockDim.x + threadIdx.x;
    if (i >= 16384) return;
    if (g_i64) s_tok[i] = (int)((const long long*)src)[i];
    else       s_tok[i] = ((const int*)src)[i];
}

__global__ void k_cvt_f(float* __restrict__ dst, const void* __restrict__ src, int n) {
    int i  = blockIdx.x * blockDim.x + threadIdx.x;
    int st = gridDim.x * blockDim.x;
    if (g_f64) {
        const double* s = (const double*)src;
        for (; i < n; i += st) dst[i] = (float)s[i];
    } else {
        const float* s = (const float*)src;
        for (; i < n; i += st) dst[i] = s[i];
    }
}

__global__ void k_reset() { if (threadIdx.x < 2) g_arrive[threadIdx.x] = 0u; }

// ---------------------------------------------------------------------------
// Embedding: direct dtype-branched gather (no vocab-wide staging)
// ---------------------------------------------------------------------------
__global__ void k_embed(const void* __restrict__ embsrc) {
    int w    = (blockIdx.x * blockDim.x + threadIdx.x) >> 5;
    int lane = threadIdx.x & 31;
    if (w >= MR) return;
    int t = w >> 5, b = w & 31;
    size_t row = (size_t)s_tok[b * LL + t];
    if (g_f64) {
        const double* src = (const double*)embsrc + row * 256;
        float*        dst = g_x0 + (size_t)w * 256;
        for (int e = lane; e < 256; e += 32) dst[e] = (float)src[e];
    } else {
        const float4* src = (const float4*)((const float*)embsrc + row * 256);
        float4*       dst = (float4*)(g_x0 + (size_t)w * 256);
        dst[lane]      = src[lane];
        dst[lane + 32] = src[lane + 32];
    }
}

// ---------------------------------------------------------------------------
// Double-buffered register-tiled GEMM: g_G[n][m] = A[m]·W[n] + bias[n]
// BM=128, BN=128, BK=16, 256 threads, 8x8 acc, one sync per k-step,
// global loads for step k+1 overlap compute of step k. Vector writeback.
// ---------------------------------------------------------------------------
__global__ void __launch_bounds__(256) k_igemm(const float* __restrict__ A,
                                               const float* __restrict__ W,
                                               const float* __restrict__ bias,
                                               int Kin) {
    __shared__ float As[2][16][132];
    __shared__ float Ws[2][16][132];

    int tid = threadIdx.x;
    int m0 = blockIdx.y * 128, n0 = blockIdx.x * 128;
    int kc4 = tid & 3, ml = tid >> 2;
    int tx = tid & 15, ty = tid >> 4;

    float acc[8][8];
#pragma unroll
    for (int i = 0; i < 8; i++)
#pragma unroll
        for (int j = 0; j < 8; j++) acc[i][j] = 0.f;

    // Preload k-step 0 into buffer 0
    float4 a0 = *(const float4*)(A + (size_t)(m0 + ml) * Kin + kc4 * 4);
    float4 a1 = *(const float4*)(A + (size_t)(m0 + ml + 64) * Kin + kc4 * 4);
    float4 w0 = *(const float4*)(W + (size_t)(n0 + ml) * Kin + kc4 * 4);
    float4 w1 = *(const float4*)(W + (size_t)(n0 + ml + 64) * Kin + kc4 * 4);
    As[0][kc4 * 4 + 0][ml] = a0.x; As[0][kc4 * 4 + 1][ml] = a0.y;
    As[0][kc4 * 4 + 2][ml] = a0.z; As[0][kc4 * 4 + 3][ml] = a0.w;
    As[0][kc4 * 4 + 0][ml + 64] = a1.x; As[0][kc4 * 4 + 1][ml + 64] = a1.y;
    As[0][kc4 * 4 + 2][ml + 64] = a1.z; As[0][kc4 * 4 + 3][ml + 64] = a1.w;
    Ws[0][kc4 * 4 + 0][ml] = w0.x; Ws[0][kc4 * 4 + 1][ml] = w0.y;
    Ws[0][kc4 * 4 + 2][ml] = w0.z; Ws[0][kc4 * 4 + 3][ml] = w0.w;
    Ws[0][kc4 * 4 + 0][ml + 64] = w1.x; Ws[0][kc4 * 4 + 1][ml + 64] = w1.y;
    Ws[0][kc4 * 4 + 2][ml + 64] = w1.z; Ws[0][kc4 * 4 + 3][ml + 64] = w1.w;
    __syncthreads();

    int nk = Kin >> 4;
    for (int it = 0; it < nk; it++) {
        int cur = it & 1;
        bool more = (it + 1 < nk);
        if (more) {
            int k0 = (it + 1) << 4;
            a0 = *(const float4*)(A + (size_t)(m0 + ml) * Kin + k0 + kc4 * 4);
            a1 = *(const float4*)(A + (size_t)(m0 + ml + 64) * Kin + k0 + kc4 * 4);
            w0 = *(const float4*)(W + (size_t)(n0 + ml) * Kin + k0 + kc4 * 4);
            w1 = *(const float4*)(W + (size_t)(n0 + ml + 64) * Kin + k0 + kc4 * 4);
        }
#pragma unroll
        for (int kk = 0; kk < 16; kk++) {
            float av[8], bv[8];
            *(float4*)(av)     = *(const float4*)&As[cur][kk][ty * 8];
            *(float4*)(av + 4) = *(const float4*)&As[cur][kk][ty * 8 + 4];
            *(float4*)(bv)     = *(const float4*)&Ws[cur][kk][tx * 8];
            *(float4*)(bv + 4) = *(const float4*)&Ws[cur][kk][tx * 8 + 4];
#pragma unroll
            for (int i = 0; i < 8; i++)
#pragma unroll
                for (int j = 0; j < 8; j++) acc[i][j] += av[i] * bv[j];
        }
        if (more) {
            int nx = cur ^ 1;
            As[nx][kc4 * 4 + 0][ml] = a0.x; As[nx][kc4 * 4 + 1][ml] = a0.y;
            As[nx][kc4 * 4 + 2][ml] = a0.z; As[nx][kc4 * 4 + 3][ml] = a0.w;
            As[nx][kc4 * 4 + 0][ml + 64] = a1.x; As[nx][kc4 * 4 + 1][ml + 64] = a1.y;
            As[nx][kc4 * 4 + 2][ml + 64] = a1.z; As[nx][kc4 * 4 + 3][ml + 64] = a1.w;
            Ws[nx][kc4 * 4 + 0][ml] = w0.x; Ws[nx][kc4 * 4 + 1][ml] = w0.y;
            Ws[nx][kc4 * 4 + 2][ml] = w0.z; Ws[nx][kc4 * 4 + 3][ml] = w0.w;
            Ws[nx][kc4 * 4 + 0][ml + 64] = w1.x; Ws[nx][kc4 * 4 + 1][ml + 64] = w1.y;
            Ws[nx][kc4 * 4 + 2][ml + 64] = w1.z; Ws[nx][kc4 * 4 + 3][ml + 64] = w1.w;
            __syncthreads();
        }
    }

    // Vectorized writeback: acc[i][j] over i is contiguous in m.
#pragma unroll
    for (int j = 0; j < 8; j++) {
        int n = n0 + tx * 8 + j;
        float bb = bias[n];
        float4 v0 = make_float4(acc[0][j] + bb, acc[1][j] + bb, acc[2][j] + bb, acc[3][j] + bb);
        float4 v1 = make_float4(acc[4][j] + bb, acc[5][j] + bb, acc[6][j] + bb, acc[7][j] + bb);
        float* base = &g_G[(size_t)n * MR + m0 + ty * 8];
        *(float4*)(base)     = v0;
        *(float4*)(base + 4) = v1;
    }
}

// ---------------------------------------------------------------------------
// Monotonic per-direction grid barrier
// ---------------------------------------------------------------------------
__device__ __forceinline__ void dir_barrier(int d, unsigned target) {
    __threadfence();
    __syncthreads();
    if (threadIdx.x == 0) {
        atomicAdd(&g_arrive[d], 1u);
        volatile unsigned* va = &g_arrive[d];
        while (*va < target) __nanosleep(32);
    }
    __syncthreads();
    __threadfence();
}

// ---------------------------------------------------------------------------
// Persistent LSTM recurrence with G-prefetch across the barrier.
// 128 blocks, d = bx/64, block owns 4 hidden units x 32 batches.
// ---------------------------------------------------------------------------
__global__ void __launch_bounds__(256) k_recur(const float* __restrict__ Whh,
                                               float* __restrict__ outbuf) {
    extern __shared__ float dsm[];
    float (*wT)[18]        = (float(*)[18])dsm;                               // [256][18]
    float (*h_sh)[32]      = (float(*)[32])(dsm + 256 * 18);                  // [256][32]
    float (*gpart)[16][32] = (float(*)[16][32])(dsm + 256 * 18 + 256 * 32);   // [2][16][32]
    float (*c_st)[32]      = (float(*)[32])(dsm + 256 * 18 + 256 * 32 + 2 * 16 * 32); // [4][32]

    int tid = threadIdx.x;
    int d   = blockIdx.x >> 6;
    int bi  = blockIdx.x & 63;
    int j0  = bi * 4;

    {
        int r = tid >> 4, cp = tid & 15;
        int q = r >> 2, jj = r & 3;
        const float* wrow = Whh + ((size_t)d * 1024 + q * 256 + j0 + jj) * 256;
#pragma unroll
        for (int c4 = 0; c4 < 4; c4++) {
            float4 v = *(const float4*)(wrow + cp * 16 + c4 * 4);
            wT[cp * 16 + c4 * 4 + 0][r] = v.x;
            wT[cp * 16 + c4 * 4 + 1][r] = v.y;
            wT[cp * 16 + c4 * 4 + 2][r] = v.z;
            wT[cp * 16 + c4 * 4 + 3][r] = v.w;
        }
        if (tid < 128) c_st[tid >> 5][tid & 31] = 0.f;
    }
    __syncthreads();

    int kh  = tid >> 7;
    int rem = tid & 127;
    int gp  = rem >> 4;
    int bp  = rem & 15;
    int b0  = bp * 2, g0l = gp * 2;

    int jj = tid >> 5, bq = tid & 31;    // valid for tid<128 consumers
    float gpre[4];
    if (tid < 128) {
        int t0 = d ? (LL - 1) : 0;
#pragma unroll
        for (int q = 0; q < 4; q++)
            gpre[q] = g_G[((size_t)d * 1024 + q * 256 + j0 + jj) * MR + (size_t)t0 * 32 + bq];
    }

    for (int s = 0; s < LL; s++) {
        int t = d ? (LL - 1 - s) : s;

        // Phase 1: stage h_prev
        if (s == 0) {
            for (int i = tid; i < 256 * 32; i += 256) ((float*)h_sh)[i] = 0.f;
        } else {
            const float4* src = (const float4*)&g_hbuf[s & 1][d][0][0];
            float4*       dst = (float4*)&h_sh[0][0];
            for (int i = tid; i < 2048; i += 256) dst[i] = __ldcg(src + i);
        }
        __syncthreads();

        // Phase 2: partial dots
        float a00 = 0.f, a01 = 0.f, a10 = 0.f, a11 = 0.f;
        for (int k = kh * 128; k < kh * 128 + 128; k++) {
            float2 hv = *(const float2*)&h_sh[k][b0];
            float w0 = wT[k][g0l], w1 = wT[k][g0l + 1];
            a00 += w0 * hv.x; a01 += w0 * hv.y;
            a10 += w1 * hv.x; a11 += w1 * hv.y;
        }
        gpart[kh][g0l][b0]         = a00;
        gpart[kh][g0l][b0 + 1]     = a01;
        gpart[kh][g0l + 1][b0]     = a10;
        gpart[kh][g0l + 1][b0 + 1] = a11;
        __syncthreads();

        // Phase 3: cell update using prefetched G
        if (tid < 128) {
            float gate[4];
#pragma unroll
            for (int q = 0; q < 4; q++) {
                int r = q * 4 + jj;
                gate[q] = gpart[0][r][bq] + gpart[1][r][bq] + gpre[q];
            }
            float ig = 1.f / (1.f + expf(-gate[0]));
            float fg = 1.f / (1.f + expf(-gate[1]));
            float gg = tanhf(gate[2]);
            float og = 1.f / (1.f + expf(-gate[3]));
            float c  = fg * c_st[jj][bq] + ig * gg;
            c_st[jj][bq] = c;
            float h = og * tanhf(c);
            g_hbuf[(s + 1) & 1][d][j0 + jj][bq] = h;
            outbuf[(size_t)(t * 32 + bq) * 512 + d * 256 + j0 + jj] = h;

            // Prefetch G for next step; latency absorbed by the barrier.
            if (s + 1 < LL) {
                int tn = d ? (LL - 2 - s) : (s + 1);
#pragma unroll
                for (int q = 0; q < 4; q++)
                    gpre[q] = g_G[((size_t)d * 1024 + q * 256 + j0 + jj) * MR + (size_t)tn * 32 + bq];
            }
        }
        dir_barrier(d, 64u * (unsigned)(s + 1));
    }
}

// ---------------------------------------------------------------------------
__global__ void k_fc(const float* __restrict__ X) {
    int w    = (blockIdx.x * blockDim.x + threadIdx.x) >> 5;
    int lane = threadIdx.x & 31;
    if (w >= MR) return;
    const float* x = X + (size_t)w * 512;
    float acc[KT];
#pragma unroll
    for (int c = 0; c < KT; c++) acc[c] = 0.f;
    for (int k = lane; k < 512; k += 32) {
        float xv = x[k];
#pragma unroll
        for (int c = 0; c < KT; c++) acc[c] += xv * s_fcw[c * 512 + k];
    }
#pragma unroll
    for (int off = 16; off; off >>= 1)
#pragma unroll
        for (int c = 0; c < KT; c++) acc[c] += __shfl_down_sync(0xffffffffu, acc[c], off);
    if (lane == 0) {
        int b = w & 31, t = w >> 5;
        float* o = g_feats + ((size_t)b * LL + t) * KT;
#pragma unroll
        for (int c = 0; c < KT; c++) o[c] = acc[c] + s_fcb[c];
    }
}

// ---------------------------------------------------------------------------
__global__ void k_viterbi() {
    __shared__ float tr[KT][KT];
    __shared__ float sc[2][KT];
    __shared__ unsigned char bp[LL - 1][KT];

    int b = blockIdx.x, tid = threadIdx.x;
    for (int i = tid; i < KT * KT; i += 32) ((float*)tr)[i] = s_tr[i];
    __syncwarp();

    const float* f = g_feats + (size_t)b * LL * KT;
    if (tid < KT) sc[0][tid] = f[tid] + tr[10][tid];   // START = 10
    __syncwarp();

    for (int t = 1; t < LL; t++) {
        int cur = t & 1, prv = cur ^ 1;
        if (tid < KT) {
            float best = -1e30f; int arg = 0;
#pragma unroll
            for (int p = 0; p < KT; p++) {
                float v = sc[prv][p] + tr[p][tid];
                if (v > best) { best = v; arg = p; }
            }
            bp[t - 1][tid] = (unsigned char)arg;
            sc[cur][tid]   = best + f[t * KT + tid];
        }
        __syncwarp();
    }
    if (tid == 0) {
        float best = -1e30f; int st = 0;
#pragma unroll
        for (int c = 0; c < KT; c++) {
            float v = sc[(LL - 1) & 1][c] + tr[c][11];  // STOP = 11
            if (v > best) { best = v; st = c; }
        }
        g_tags[b * LL + (LL - 1)] = st;
        for (int i = LL - 2; i >= 0; i--) {
            st = bp[i][st];
            g_tags[b * LL + i] = st;
        }
    }
}

// Float output — the R14 fix.
__global__ void k_out(void* __restrict__ out) {
    int i = blockIdx.x * blockDim.x + threadIdx.x;
    if (i >= MR) return;
    if (g_f64) ((double*)out)[i] = (double)g_tags[i];
    else       ((float*)out)[i]  = (float)g_tags[i];
}

// ---------------------------------------------------------------------------
extern "C" void kernel_launch(void* const* d_in, const int* in_sizes, int n_in,
                              void* d_out, int out_size) {
    const void* tokens = d_in[0];
    const void* embed  = d_in[1];
    const void* w_ih0  = d_in[2];
    const void* w_hh0  = d_in[3];
    const void* b0     = d_in[4];
    const void* w_ih   = d_in[5];
    const void* w_hh   = d_in[6];
    const void* bvec   = d_in[7];
    const void* fc_w   = d_in[8];
    const void* fc_b   = d_in[9];
    const void* trans  = d_in[10];

    float *p_wih0, *p_whh0, *p_b0, *p_wih, *p_whh, *p_b, *p_fcw, *p_fcb, *p_tr;
    float *px0, *pbuf;
    cudaGetSymbolAddress((void**)&p_wih0, s_wih0);
    cudaGetSymbolAddress((void**)&p_whh0, s_whh0);
    cudaGetSymbolAddress((void**)&p_b0,   s_b0);
    cudaGetSymbolAddress((void**)&p_wih,  s_wih);
    cudaGetSymbolAddress((void**)&p_whh,  s_whh);
    cudaGetSymbolAddress((void**)&p_b,    s_b);
    cudaGetSymbolAddress((void**)&p_fcw,  s_fcw);
    cudaGetSymbolAddress((void**)&p_fcb,  s_fcb);
    cudaGetSymbolAddress((void**)&p_tr,   s_tr);
    cudaGetSymbolAddress((void**)&px0,    g_x0);
    cudaGetSymbolAddress((void**)&pbuf,   g_buf);
    float* pbuf0 = pbuf;
    float* pbuf1 = pbuf + (size_t)MR * 512;

    const int recur_smem = (256 * 18 + 256 * 32 + 2 * 16 * 32 + 4 * 32) * (int)sizeof(float);
    cudaFuncSetAttribute(k_recur, cudaFuncAttributeMaxDynamicSharedMemorySize, recur_smem);

    // 1) Sniff + convert (no vocab-wide embed staging)
    k_init_flags<<<1, 32>>>();
    k_sniff_tok<<<32, 256>>>(tokens);
    k_sniff_f<<<64, 256>>>(embed);
    k_cvt_tok<<<64, 256>>>(tokens);
    k_cvt_f<<<128, 256>>>(p_wih0, w_ih0, 524288);
    k_cvt_f<<<128, 256>>>(p_whh0, w_hh0, 524288);
    k_cvt_f<<<8, 256>>>(p_b0, b0, 2048);
    k_cvt_f<<<256, 256>>>(p_wih, w_ih, 3145728);
    k_cvt_f<<<128, 256>>>(p_whh, w_hh, 1572864);
    k_cvt_f<<<8, 256>>>(p_b, bvec, 6144);
    k_cvt_f<<<8, 256>>>(p_fcw, fc_w, 6144);
    k_cvt_f<<<1, 32>>>(p_fcb, fc_b, 12);
    k_cvt_f<<<1, 256>>>(p_tr, trans, 144);

    // 2) Pipeline
    k_embed<<<2048, 256>>>(embed);

    k_igemm<<<dim3(16, 128), 256>>>(px0, p_wih0, p_b0, 256);
    k_reset<<<1, 32>>>();
    k_recur<<<128, 256, recur_smem>>>(p_whh0, pbuf0);

    const float* ins[3]  = {pbuf0, pbuf1, pbuf0};
    float*       outs[3] = {pbuf1, pbuf0, pbuf1};
    for (int l = 1; l <= 3; l++) {
        k_igemm<<<dim3(16, 128), 256>>>(ins[l - 1],
                                        p_wih + (size_t)(l - 1) * 2 * 1024 * 512,
                                        p_b + (size_t)(l - 1) * 2 * 1024, 512);
        k_reset<<<1, 32>>>();
        k_recur<<<128, 256, recur_smem>>>(p_whh + (size_t)(l - 1) * 2 * 1024 * 256,
                                          outs[l - 1]);
    }

    k_fc<<<2048, 256>>>(pbuf1);
    k_viterbi<<<BB, 32>>>();
    k_out<<<64, 256>>>(d_out);
}

// round 17
// speedup vs baseline: 21.6570x; 1.1070x over previous
#include <cuda_runtime.h>
#include <cstdint>
#include <math.h>

#define LL 512
#define BB 32
#define KT 12
#define MR (LL*BB)

// ---------------------------------------------------------------------------
// Packed f32x2 helpers (sm_100a: 2-wide fp32 FMA pipe, IEEE per lane)
// ---------------------------------------------------------------------------
__device__ __forceinline__ void fma2(unsigned long long& d, unsigned long long a,
                                     unsigned long long b) {
    asm("fma.rn.f32x2 %0, %1, %2, %0;" : "+l"(d) : "l"(a), "l"(b));
}
__device__ __forceinline__ unsigned long long splat2(float x) {
    unsigned long long r;
    asm("mov.b64 %0, {%1, %1};" : "=l"(r) : "f"(x));
    return r;
}
union F4U2 { float4 f; unsigned long long u[2]; };
union F2U1 { float2 f; unsigned long long u; };

// ---------------------------------------------------------------------------
// Scratch + staging (static; no allocations)
// ---------------------------------------------------------------------------
__device__ float g_x0[MR * 256];
__device__ float g_buf[2][(size_t)MR * 512];
__device__ float g_G[(size_t)2048 * MR];        // gate-major [n][m], bias included
__device__ float g_feats[(size_t)MR * KT];
__device__ int   g_tags[MR];
__device__ float g_hbuf[2][2][256][32];         // h double-buffer [par][dir][j][b]
__device__ unsigned g_leaf[16];                 // [d*8 + group] hierarchical barrier
__device__ unsigned g_root[2];

__device__ int   g_i64;
__device__ int   g_f64;

__device__ int   s_tok[16384];
__device__ float s_wih0[524288];
__device__ float s_whh0[524288];
__device__ float s_b0[2048];
__device__ float s_wih[3145728];
__device__ float s_whh[1572864];
__device__ float s_b[6144];
__device__ float s_fcw[6144];
__device__ float s_fcb[12];
__device__ float s_tr[144];

// ---------------------------------------------------------------------------
// Dtype sniffers + converters (proven R14-R16)
// ---------------------------------------------------------------------------
__global__ void k_init_flags() {
    int t = threadIdx.x;
    if (t == 0) { g_i64 = 1; g_f64 = 0; }
    if (t < 16) g_leaf[t] = 0u;
    if (t < 2)  g_root[t] = 0u;
}

__global__ void k_sniff_tok(const void* __restrict__ tok) {
    const int* p = (const int*)tok;
    int i = blockIdx.x * blockDim.x + threadIdx.x;
    if (i < 8192) {
        int lo = p[2 * i], hi = p[2 * i + 1];
        if (hi != 0 || lo < 0 || lo >= 50000) g_i64 = 0;
    }
}

__global__ void k_sniff_f(const void* __restrict__ emb) {
    const float* p = (const float*)emb;
    int i = blockIdx.x * blockDim.x + threadIdx.x;
    if (i < 16384) {
        float v = p[i];
        if (!isfinite(v) || fabsf(v) > 100.f) g_f64 = 1;
    }
}

__global__ void k_cvt_tok(const void* __restrict__ src) {
    int i = blockIdx.x * blockDim.x + threadIdx.x;
    if (i >= 16384) return;
    if (g_i64) s_tok[i] = (int)((const long long*)src)[i];
    else       s_tok[i] = ((const int*)src)[i];
}

__global__ void k_cvt_f(float* __restrict__ dst, const void* __restrict__ src, int n) {
    int i  = blockIdx.x * blockDim.x + threadIdx.x;
    int st = gridDim.x * blockDim.x;
    if (g_f64) {
        const double* s = (const double*)src;
        for (; i < n; i += st) dst[i] = (float)s[i];
    } else {
        const float* s = (const float*)src;
        for (; i < n; i += st) dst[i] = s[i];
    }
}

__global__ void k_reset() {
    if (threadIdx.x < 16) g_leaf[threadIdx.x] = 0u;
    if (threadIdx.x < 2)  g_root[threadIdx.x] = 0u;
}

// ---------------------------------------------------------------------------
// Embedding: direct dtype-branched gather
// ---------------------------------------------------------------------------
__global__ void k_embed(const void* __restrict__ embsrc) {
    int w    = (blockIdx.x * blockDim.x + threadIdx.x) >> 5;
    int lane = threadIdx.x & 31;
    if (w >= MR) return;
    int t = w >> 5, b = w & 31;
    size_t row = (size_t)s_tok[b * LL + t];
    if (g_f64) {
        const double* src = (const double*)embsrc + row * 256;
        float*        dst = g_x0 + (size_t)w * 256;
        for (int e = lane; e < 256; e += 32) dst[e] = (float)src[e];
    } else {
        const float4* src = (const float4*)((const float*)embsrc + row * 256);
        float4*       dst = (float4*)(g_x0 + (size_t)w * 256);
        dst[lane]      = src[lane];
        dst[lane + 32] = src[lane + 32];
    }
}

// ---------------------------------------------------------------------------
// Double-buffered GEMM with packed f32x2 FMA: g_G[n][m] = A[m]·W[n] + bias[n]
// ---------------------------------------------------------------------------
__global__ void __launch_bounds__(256) k_igemm(const float* __restrict__ A,
                                               const float* __restrict__ W,
                                               const float* __restrict__ bias,
                                               int Kin) {
    __shared__ float As[2][16][132];
    __shared__ float Ws[2][16][132];

    int tid = threadIdx.x;
    int m0 = blockIdx.y * 128, n0 = blockIdx.x * 128;
    int kc4 = tid & 3, ml = tid >> 2;
    int tx = tid & 15, ty = tid >> 4;

    unsigned long long acc2[8][4];
#pragma unroll
    for (int i = 0; i < 8; i++)
#pragma unroll
        for (int j = 0; j < 4; j++) acc2[i][j] = 0ull;

    float4 a0 = *(const float4*)(A + (size_t)(m0 + ml) * Kin + kc4 * 4);
    float4 a1 = *(const float4*)(A + (size_t)(m0 + ml + 64) * Kin + kc4 * 4);
    float4 w0 = *(const float4*)(W + (size_t)(n0 + ml) * Kin + kc4 * 4);
    float4 w1 = *(const float4*)(W + (size_t)(n0 + ml + 64) * Kin + kc4 * 4);
    As[0][kc4 * 4 + 0][ml] = a0.x; As[0][kc4 * 4 + 1][ml] = a0.y;
    As[0][kc4 * 4 + 2][ml] = a0.z; As[0][kc4 * 4 + 3][ml] = a0.w;
    As[0][kc4 * 4 + 0][ml + 64] = a1.x; As[0][kc4 * 4 + 1][ml + 64] = a1.y;
    As[0][kc4 * 4 + 2][ml + 64] = a1.z; As[0][kc4 * 4 + 3][ml + 64] = a1.w;
    Ws[0][kc4 * 4 + 0][ml] = w0.x; Ws[0][kc4 * 4 + 1][ml] = w0.y;
    Ws[0][kc4 * 4 + 2][ml] = w0.z; Ws[0][kc4 * 4 + 3][ml] = w0.w;
    Ws[0][kc4 * 4 + 0][ml + 64] = w1.x; Ws[0][kc4 * 4 + 1][ml + 64] = w1.y;
    Ws[0][kc4 * 4 + 2][ml + 64] = w1.z; Ws[0][kc4 * 4 + 3][ml + 64] = w1.w;
    __syncthreads();

    int nk = Kin >> 4;
    for (int it = 0; it < nk; it++) {
        int cur = it & 1;
        bool more = (it + 1 < nk);
        if (more) {
            int k0 = (it + 1) << 4;
            a0 = *(const float4*)(A + (size_t)(m0 + ml) * Kin + k0 + kc4 * 4);
            a1 = *(const float4*)(A + (size_t)(m0 + ml + 64) * Kin + k0 + kc4 * 4);
            w0 = *(const float4*)(W + (size_t)(n0 + ml) * Kin + k0 + kc4 * 4);
            w1 = *(const float4*)(W + (size_t)(n0 + ml + 64) * Kin + k0 + kc4 * 4);
        }
#pragma unroll
        for (int kk = 0; kk < 16; kk++) {
            float av[8];
            *(float4*)(av)     = *(const float4*)&As[cur][kk][ty * 8];
            *(float4*)(av + 4) = *(const float4*)&As[cur][kk][ty * 8 + 4];
            F4U2 bl, bh;
            bl.f = *(const float4*)&Ws[cur][kk][tx * 8];
            bh.f = *(const float4*)&Ws[cur][kk][tx * 8 + 4];
            unsigned long long bv2[4] = {bl.u[0], bl.u[1], bh.u[0], bh.u[1]};
#pragma unroll
            for (int i = 0; i < 8; i++) {
                unsigned long long as2 = splat2(av[i]);
#pragma unroll
                for (int j = 0; j < 4; j++) fma2(acc2[i][j], as2, bv2[j]);
            }
        }
        if (more) {
            int nx = cur ^ 1;
            As[nx][kc4 * 4 + 0][ml] = a0.x; As[nx][kc4 * 4 + 1][ml] = a0.y;
            As[nx][kc4 * 4 + 2][ml] = a0.z; As[nx][kc4 * 4 + 3][ml] = a0.w;
            As[nx][kc4 * 4 + 0][ml + 64] = a1.x; As[nx][kc4 * 4 + 1][ml + 64] = a1.y;
            As[nx][kc4 * 4 + 2][ml + 64] = a1.z; As[nx][kc4 * 4 + 3][ml + 64] = a1.w;
            Ws[nx][kc4 * 4 + 0][ml] = w0.x; Ws[nx][kc4 * 4 + 1][ml] = w0.y;
            Ws[nx][kc4 * 4 + 2][ml] = w0.z; Ws[nx][kc4 * 4 + 3][ml] = w0.w;
            Ws[nx][kc4 * 4 + 0][ml + 64] = w1.x; Ws[nx][kc4 * 4 + 1][ml + 64] = w1.y;
            Ws[nx][kc4 * 4 + 2][ml + 64] = w1.z; Ws[nx][kc4 * 4 + 3][ml + 64] = w1.w;
            __syncthreads();
        }
    }

    // Unpack + vectorized writeback (acc over i is contiguous in m)
#pragma unroll
    for (int j2 = 0; j2 < 4; j2++) {
#pragma unroll
        for (int jo = 0; jo < 2; jo++) {
            int j = 2 * j2 + jo;
            int n = n0 + tx * 8 + j;
            float bb = bias[n];
            float e[8];
#pragma unroll
            for (int i = 0; i < 8; i++) {
                F2U1 u; u.u = acc2[i][j2];
                e[i] = (jo == 0 ? u.f.x : u.f.y) + bb;
            }
            float* base = &g_G[(size_t)n * MR + m0 + ty * 8];
            *(float4*)(base)     = make_float4(e[0], e[1], e[2], e[3]);
            *(float4*)(base + 4) = make_float4(e[4], e[5], e[6], e[7]);
        }
    }
}

// ---------------------------------------------------------------------------
// Hierarchical per-direction grid barrier: 8 leaves x 8 arrivals + root.
// Monotonic counters (reset per layer by k_reset) -> no reuse races.
// ---------------------------------------------------------------------------
__device__ __forceinline__ void dir_barrier(int d, int bi, unsigned s1) {
    __threadfence();
    __syncthreads();
    if (threadIdx.x == 0) {
        unsigned old = atomicAdd(&g_leaf[d * 8 + (bi >> 3)], 1u);
        if ((old & 7u) == 7u) atomicAdd(&g_root[d], 1u);
        volatile unsigned* vr = &g_root[d];
        while (*vr < 8u * s1) __nanosleep(32);
    }
    __syncthreads();
    __threadfence();
}

// ---------------------------------------------------------------------------
// Persistent LSTM recurrence, f32x2 phase 2.
// 128 blocks, d = bx/64, block owns 4 hidden units (16 gate rows) x 32 b.
// Thread map: kq = tid/64 (k-quarter), rp = (tid/8)%8 (row pair), bq = tid%8.
// ---------------------------------------------------------------------------
__global__ void __launch_bounds__(256) k_recur(const float* __restrict__ Whh,
                                               float* __restrict__ outbuf) {
    extern __shared__ float dsm[];
    float (*wT)[18]        = (float(*)[18])dsm;                               // [256][18]
    float (*h_sh)[32]      = (float(*)[32])(dsm + 256 * 18);                  // [256][32]
    float (*gpart)[16][32] = (float(*)[16][32])(dsm + 256 * 18 + 256 * 32);   // [4][16][32]
    float (*c_st)[32]      = (float(*)[32])(dsm + 256 * 18 + 256 * 32 + 4 * 16 * 32); // [4][32]

    int tid = threadIdx.x;
    int d   = blockIdx.x >> 6;
    int bi  = blockIdx.x & 63;
    int j0  = bi * 4;

    // Load Whh slice transposed: wT[k][r], r = q*4+jj -> gate row q*256+j0+jj
    {
        int r = tid >> 4, cp = tid & 15;
        int q = r >> 2, jj = r & 3;
        const float* wrow = Whh + ((size_t)d * 1024 + q * 256 + j0 + jj) * 256;
#pragma unroll
        for (int c4 = 0; c4 < 4; c4++) {
            float4 v = *(const float4*)(wrow + cp * 16 + c4 * 4);
            wT[cp * 16 + c4 * 4 + 0][r] = v.x;
            wT[cp * 16 + c4 * 4 + 1][r] = v.y;
            wT[cp * 16 + c4 * 4 + 2][r] = v.z;
            wT[cp * 16 + c4 * 4 + 3][r] = v.w;
        }
        if (tid < 128) c_st[tid >> 5][tid & 31] = 0.f;
    }
    __syncthreads();

    int kq  = tid >> 6;             // k-quarter 0..3
    int rem = tid & 63;
    int rp  = rem >> 3;             // row pair 0..7
    int bqt = rem & 7;              // batch quad 0..7
    int g0l = rp * 2, b0 = bqt * 4;
    int kst = kq * 64;

    int jj = tid >> 5, bq = tid & 31;    // phase-3 mapping (tid<128)
    float gpre[4];
    if (tid < 128) {
        int t0 = d ? (LL - 1) : 0;
#pragma unroll
        for (int q = 0; q < 4; q++)
            gpre[q] = g_G[((size_t)d * 1024 + q * 256 + j0 + jj) * MR + (size_t)t0 * 32 + bq];
    }

    for (int s = 0; s < LL; s++) {
        int t = d ? (LL - 1 - s) : s;

        // Phase 1: stage h_prev
        if (s == 0) {
            for (int i = tid; i < 256 * 32; i += 256) ((float*)h_sh)[i] = 0.f;
        } else {
            const float4* src = (const float4*)&g_hbuf[s & 1][d][0][0];
            float4*       dst = (float4*)&h_sh[0][0];
            for (int i = tid; i < 2048; i += 256) dst[i] = __ldcg(src + i);
        }
        __syncthreads();

        // Phase 2: packed partial dots — 2 rows x 4 batches x 64 k per thread
        unsigned long long p00 = 0ull, p01 = 0ull, p10 = 0ull, p11 = 0ull;
#pragma unroll 4
        for (int k = kst; k < kst + 64; k++) {
            F4U2 h4; h4.f = *(const float4*)&h_sh[k][b0];
            F2U1 w2; w2.f = *(const float2*)&wT[k][g0l];
            unsigned long long w0s = splat2(w2.f.x);
            unsigned long long w1s = splat2(w2.f.y);
            fma2(p00, w0s, h4.u[0]); fma2(p01, w0s, h4.u[1]);
            fma2(p10, w1s, h4.u[0]); fma2(p11, w1s, h4.u[1]);
        }
        { F2U1 u; u.u = p00; *(float2*)&gpart[kq][g0l][b0]         = u.f; }
        { F2U1 u; u.u = p01; *(float2*)&gpart[kq][g0l][b0 + 2]     = u.f; }
        { F2U1 u; u.u = p10; *(float2*)&gpart[kq][g0l + 1][b0]     = u.f; }
        { F2U1 u; u.u = p11; *(float2*)&gpart[kq][g0l + 1][b0 + 2] = u.f; }
        __syncthreads();

        // Phase 3: cell update (128 threads: 4 hidden x 32 batches)
        if (tid < 128) {
            float gate[4];
#pragma unroll
            for (int q = 0; q < 4; q++) {
                int r = q * 4 + jj;
                gate[q] = gpart[0][r][bq] + gpart[1][r][bq] +
                          gpart[2][r][bq] + gpart[3][r][bq] + gpre[q];
            }
            float ig = 1.f / (1.f + expf(-gate[0]));
            float fg = 1.f / (1.f + expf(-gate[1]));
            float gg = tanhf(gate[2]);
            float og = 1.f / (1.f + expf(-gate[3]));
            float c  = fg * c_st[jj][bq] + ig * gg;
            c_st[jj][bq] = c;
            float h = og * tanhf(c);
            g_hbuf[(s + 1) & 1][d][j0 + jj][bq] = h;
            outbuf[(size_t)(t * 32 + bq) * 512 + d * 256 + j0 + jj] = h;

            if (s + 1 < LL) {
                int tn = d ? (LL - 2 - s) : (s + 1);
#pragma unroll
                for (int q = 0; q < 4; q++)
                    gpre[q] = g_G[((size_t)d * 1024 + q * 256 + j0 + jj) * MR + (size_t)tn * 32 + bq];
            }
        }
        dir_barrier(d, bi, (unsigned)(s + 1));
    }
}

// ---------------------------------------------------------------------------
__global__ void k_fc(const float* __restrict__ X) {
    int w    = (blockIdx.x * blockDim.x + threadIdx.x) >> 5;
    int lane = threadIdx.x & 31;
    if (w >= MR) return;
    const float* x = X + (size_t)w * 512;
    float acc[KT];
#pragma unroll
    for (int c = 0; c < KT; c++) acc[c] = 0.f;
    for (int k = lane; k < 512; k += 32) {
        float xv = x[k];
#pragma unroll
        for (int c = 0; c < KT; c++) acc[c] += xv * s_fcw[c * 512 + k];
    }
#pragma unroll
    for (int off = 16; off; off >>= 1)
#pragma unroll
        for (int c = 0; c < KT; c++) acc[c] += __shfl_down_sync(0xffffffffu, acc[c], off);
    if (lane == 0) {
        int b = w & 31, t = w >> 5;
        float* o = g_feats + ((size_t)b * LL + t) * KT;
#pragma unroll
        for (int c = 0; c < KT; c++) o[c] = acc[c] + s_fcb[c];
    }
}

// ---------------------------------------------------------------------------
__global__ void k_viterbi() {
    __shared__ float tr[KT][KT];
    __shared__ float sc[2][KT];
    __shared__ unsigned char bp[LL - 1][KT];

    int b = blockIdx.x, tid = threadIdx.x;
    for (int i = tid; i < KT * KT; i += 32) ((float*)tr)[i] = s_tr[i];
    __syncwarp();

    const float* f = g_feats + (size_t)b * LL * KT;
    if (tid < KT) sc[0][tid] = f[tid] + tr[10][tid];   // START = 10
    __syncwarp();

    for (int t = 1; t < LL; t++) {
        int cur = t & 1, prv = cur ^ 1;
        if (tid < KT) {
            float best = -1e30f; int arg = 0;
#pragma unroll
            for (int p = 0; p < KT; p++) {
                float v = sc[prv][p] + tr[p][tid];
                if (v > best) { best = v; arg = p; }
            }
            bp[t - 1][tid] = (unsigned char)arg;
            sc[cur][tid]   = best + f[t * KT + tid];
        }
        __syncwarp();
    }
    if (tid == 0) {
        float best = -1e30f; int st = 0;
#pragma unroll
        for (int c = 0; c < KT; c++) {
            float v = sc[(LL - 1) & 1][c] + tr[c][11];  // STOP = 11
            if (v > best) { best = v; st = c; }
        }
        g_tags[b * LL + (LL - 1)] = st;
        for (int i = LL - 2; i >= 0; i--) {
            st = bp[i][st];
            g_tags[b * LL + i] = st;
        }
    }
}

// Float output — the R14 fix.
__global__ void k_out(void* __restrict__ out) {
    int i = blockIdx.x * blockDim.x + threadIdx.x;
    if (i >= MR) return;
    if (g_f64) ((double*)out)[i] = (double)g_tags[i];
    else       ((float*)out)[i]  = (float)g_tags[i];
}

// ---------------------------------------------------------------------------
extern "C" void kernel_launch(void* const* d_in, const int* in_sizes, int n_in,
                              void* d_out, int out_size) {
    const void* tokens = d_in[0];
    const void* embed  = d_in[1];
    const void* w_ih0  = d_in[2];
    const void* w_hh0  = d_in[3];
    const void* b0     = d_in[4];
    const void* w_ih   = d_in[5];
    const void* w_hh   = d_in[6];
    const void* bvec   = d_in[7];
    const void* fc_w   = d_in[8];
    const void* fc_b   = d_in[9];
    const void* trans  = d_in[10];

    float *p_wih0, *p_whh0, *p_b0, *p_wih, *p_whh, *p_b, *p_fcw, *p_fcb, *p_tr;
    float *px0, *pbuf;
    cudaGetSymbolAddress((void**)&p_wih0, s_wih0);
    cudaGetSymbolAddress((void**)&p_whh0, s_whh0);
    cudaGetSymbolAddress((void**)&p_b0,   s_b0);
    cudaGetSymbolAddress((void**)&p_wih,  s_wih);
    cudaGetSymbolAddress((void**)&p_whh,  s_whh);
    cudaGetSymbolAddress((void**)&p_b,    s_b);
    cudaGetSymbolAddress((void**)&p_fcw,  s_fcw);
    cudaGetSymbolAddress((void**)&p_fcb,  s_fcb);
    cudaGetSymbolAddress((void**)&p_tr,   s_tr);
    cudaGetSymbolAddress((void**)&px0,    g_x0);
    cudaGetSymbolAddress((void**)&pbuf,   g_buf);
    float* pbuf0 = pbuf;
    float* pbuf1 = pbuf + (size_t)MR * 512;

    const int recur_smem = (256 * 18 + 256 * 32 + 4 * 16 * 32 + 4 * 32) * (int)sizeof(float);
    cudaFuncSetAttribute(k_recur, cudaFuncAttributeMaxDynamicSharedMemorySize, recur_smem);

    // 1) Sniff + convert
    k_init_flags<<<1, 32>>>();
    k_sniff_tok<<<32, 256>>>(tokens);
    k_sniff_f<<<64, 256>>>(embed);
    k_cvt_tok<<<64, 256>>>(tokens);
    k_cvt_f<<<128, 256>>>(p_wih0, w_ih0, 524288);
    k_cvt_f<<<128, 256>>>(p_whh0, w_hh0, 524288);
    k_cvt_f<<<8, 256>>>(p_b0, b0, 2048);
    k_cvt_f<<<256, 256>>>(p_wih, w_ih, 3145728);
    k_cvt_f<<<128, 256>>>(p_whh, w_hh, 1572864);
    k_cvt_f<<<8, 256>>>(p_b, bvec, 6144);
    k_cvt_f<<<8, 256>>>(p_fcw, fc_w, 6144);
    k_cvt_f<<<1, 32>>>(p_fcb, fc_b, 12);
    k_cvt_f<<<1, 256>>>(p_tr, trans, 144);

    // 2) Pipeline
    k_embed<<<2048, 256>>>(embed);

    k_igemm<<<dim3(16, 128), 256>>>(px0, p_wih0, p_b0, 256);
    k_reset<<<1, 32>>>();
    k_recur<<<128, 256, recur_smem>>>(p_whh0, pbuf0);

    const float* ins[3]  = {pbuf0, pbuf1, pbuf0};
    float*       outs[3] = {pbuf1, pbuf0, pbuf1};
    for (int l = 1; l <= 3; l++) {
        k_igemm<<<dim3(16, 128), 256>>>(ins[l - 1],
                                        p_wih + (size_t)(l - 1) * 2 * 1024 * 512,
                                        p_b + (size_t)(l - 1) * 2 * 1024, 512);
        k_reset<<<1, 32>>>();
        k_recur<<<128, 256, recur_smem>>>(p_whh + (size_t)(l - 1) * 2 * 1024 * 256,
                                          outs[l - 1]);
    }

    k_fc<<<2048, 256>>>(pbuf1);
    k_viterbi<<<BB, 32>>>();
    k_out<<<64, 256>>>(d_out);
}